// round 12
// baseline (speedup 1.0000x reference)
#include <cuda_runtime.h>

#define NN 8192
#define EE 16384
#define EE4 (EE / 4)

// g_uv[0..EE) = u = e.*(Ro^T a);  g_uv[EE..2EE) = v = e.*(Ri^T b)
__device__ float g_uv[2 * EE];
__device__ unsigned int g_ticket;   // phase C tile dispatcher

// ---------------- Phase A: u from Ro (column reduce, DUAL stream) ----------
// Each thread owns columns e and e+EE/2: two independent LDG streams per
// thread (MLP like R8-phase1, which sustained 6.85 TB/s).
#define PA_CHUNK 128
__global__ __launch_bounds__(256) void phaseA(
    const float4* __restrict__ X4, const float* __restrict__ ker,
    const float* __restrict__ Ro, const float* __restrict__ ev)
{
    __shared__ float sa[PA_CHUNK];
    int tid = threadIdx.x;
    int e0  = blockIdx.x * 256 + tid;
    int e1  = e0 + EE / 2;
    int n0  = blockIdx.y * PA_CHUNK;

    if (tid < PA_CHUNK) {
        float4 x = X4[n0 + tid];
        sa[tid] = x.x * ker[0] + x.y * ker[1] + x.z * ker[2] + x.w * ker[3];
    }
    __syncthreads();

    const float* r0 = Ro + (size_t)n0 * EE + e0;
    const float* r1 = Ro + (size_t)n0 * EE + e1;
    float s0 = 0.0f, s1 = 0.0f;
#pragma unroll 8
    for (int j = 0; j < PA_CHUNK; j++) {
        float A = sa[j];
        s0 += __ldcs(r0 + (size_t)j * EE) * A;
        s1 += __ldcs(r1 + (size_t)j * EE) * A;
    }
    atomicAdd(&g_uv[e0], ev[e0] * s0);
    atomicAdd(&g_uv[e1], ev[e1] * s1);
}

// ---------------- Phase B: single pass over Ri (DUAL stream, fused) --------
// One load of Ri feeds BOTH  v[e] += Ri[n,e]*b[n]  and  out[n] += Ri[n,e]*u[e].
// Each thread owns float4 column groups e4 and e4+EE4/2: 2 LDG.128 streams,
// and each shfl butterfly now reduces 32 bytes of row contribution.
__global__ __launch_bounds__(256) void phaseB(
    const float4* __restrict__ X4, const float* __restrict__ ker,
    const float4* __restrict__ Ri4, const float4* __restrict__ ev4,
    float* __restrict__ out)
{
    __shared__ float sb[128];
    __shared__ float sred[128][8];
    int tid  = threadIdx.x;
    int lane = tid & 31;
    int wid  = tid >> 5;
    int e40  = blockIdx.x * 256 + tid;        // float4 column index, stream 0
    int e41  = e40 + EE4 / 2;                 // stream 1
    int n0   = blockIdx.y * 128;

    if (tid < 128) {
        float4 x = X4[n0 + tid];
        sb[tid] = x.x * ker[4] + x.y * ker[5] + x.z * ker[6] + x.w * ker[7];
    }
    __syncthreads();

    float4 u0 = *reinterpret_cast<const float4*>(&g_uv[4 * e40]);  // final after A
    float4 u1 = *reinterpret_cast<const float4*>(&g_uv[4 * e41]);
    float4 si0 = make_float4(0.f, 0.f, 0.f, 0.f);
    float4 si1 = make_float4(0.f, 0.f, 0.f, 0.f);
    const float4* ri0 = Ri4 + (size_t)n0 * EE4 + e40;
    const float4* ri1 = Ri4 + (size_t)n0 * EE4 + e41;

#pragma unroll 4
    for (int j = 0; j < 128; j++) {
        float4 t0 = __ldcs(ri0 + (size_t)j * EE4);
        float4 t1 = __ldcs(ri1 + (size_t)j * EE4);
        float B = sb[j];
        si0.x += t0.x * B; si0.y += t0.y * B; si0.z += t0.z * B; si0.w += t0.w * B;
        si1.x += t1.x * B; si1.y += t1.y * B; si1.z += t1.z * B; si1.w += t1.w * B;
        float r = t0.x * u0.x + t0.y * u0.y + t0.z * u0.z + t0.w * u0.w
                + t1.x * u1.x + t1.y * u1.y + t1.z * u1.z + t1.w * u1.w;
        r += __shfl_xor_sync(0xffffffffu, r, 16);
        r += __shfl_xor_sync(0xffffffffu, r, 8);
        r += __shfl_xor_sync(0xffffffffu, r, 4);
        r += __shfl_xor_sync(0xffffffffu, r, 2);
        r += __shfl_xor_sync(0xffffffffu, r, 1);
        if (lane == 0) sred[j][wid] = r;
    }

    float4 w0 = ev4[e40];
    float4 w1 = ev4[e41];
    int a0 = EE + 4 * e40;
    int a1 = EE + 4 * e41;
    atomicAdd(&g_uv[a0 + 0], w0.x * si0.x);
    atomicAdd(&g_uv[a0 + 1], w0.y * si0.y);
    atomicAdd(&g_uv[a0 + 2], w0.z * si0.z);
    atomicAdd(&g_uv[a0 + 3], w0.w * si0.w);
    atomicAdd(&g_uv[a1 + 0], w1.x * si1.x);
    atomicAdd(&g_uv[a1 + 1], w1.y * si1.y);
    atomicAdd(&g_uv[a1 + 2], w1.z * si1.z);
    atomicAdd(&g_uv[a1 + 3], w1.w * si1.w);

    __syncthreads();
    if (tid < 128) {
        float val = sred[tid][0] + sred[tid][1] + sred[tid][2] + sred[tid][3]
                  + sred[tid][4] + sred[tid][5] + sred[tid][6] + sred[tid][7];
        atomicAdd(&out[n0 + tid], val);
    }
}

// ---------------- Phase C: out += Ro.v + c (UNCHANGED, proven) -------------
#define RPB 4
#define NTILES (NN / RPB)
#define PC_BLOCKS (148 * 4)
__global__ __launch_bounds__(256) void phaseC(
    const float4* __restrict__ X4, const float* __restrict__ ker,
    const float4* __restrict__ Ro4, float* __restrict__ out)
{
    __shared__ float red[RPB][256];
    __shared__ int sTile;
    int tid = threadIdx.x;

    const float4* v4 = reinterpret_cast<const float4*>(g_uv) + EE4;

    for (;;) {
        if (tid == 0) sTile = (int)atomicAdd(&g_ticket, 1u);
        __syncthreads();
        int tile = sTile;
        if (tile >= NTILES) break;
        int n0 = tile * RPB;

        float s[RPB];
#pragma unroll
        for (int r = 0; r < RPB; r++) s[r] = 0.0f;

#pragma unroll 4
        for (int it = 0; it < EE4 / 256; it++) {
            int e4 = it * 256 + tid;
            float4 v = v4[e4];                 // L2-hot (64 KB)
#pragma unroll
            for (int r = 0; r < RPB; r++) {
                float4 b = __ldcs(Ro4 + (size_t)(n0 + r) * EE4 + e4);
                s[r] += b.x * v.x + b.y * v.y + b.z * v.z + b.w * v.w;
            }
        }

#pragma unroll
        for (int r = 0; r < RPB; r++) red[r][tid] = s[r];
        __syncthreads();
        for (int st = 128; st > 0; st >>= 1) {
            if (tid < st) {
#pragma unroll
                for (int r = 0; r < RPB; r++) red[r][tid] += red[r][tid + st];
            }
            __syncthreads();
        }
        if (tid < RPB) {
            int n = n0 + tid;
            float4 x = X4[n];
            out[n] = out[n] + red[tid][0]      // out already holds Ri.u from B
                   + x.x * ker[8] + x.y * ker[9] + x.z * ker[10] + x.w * ker[11];
        }
        __syncthreads();
    }
}

extern "C" void kernel_launch(void* const* d_in, const int* in_sizes, int n_in,
                              void* d_out, int out_size) {
    const float4* X4  = (const float4*)d_in[0];
    const float*  ev  = (const float*)d_in[1];
    const float*  Ri  = (const float*)d_in[2];
    const float*  Ro  = (const float*)d_in[3];
    const float*  ker = (const float*)d_in[4];
    float* out = (float*)d_out;

    void* uvptr = nullptr;
    cudaGetSymbolAddress(&uvptr, g_uv);
    cudaMemsetAsync(uvptr, 0, 2 * EE * sizeof(float));
    void* tkptr = nullptr;
    cudaGetSymbolAddress(&tkptr, g_ticket);
    cudaMemsetAsync(tkptr, 0, sizeof(unsigned int));
    cudaMemsetAsync(out, 0, (size_t)out_size * sizeof(float));

    dim3 gA(EE / 2 / 256, NN / PA_CHUNK);   // (32, 64) — dual column stream
    phaseA<<<gA, 256>>>(X4, ker, Ro, ev);

    dim3 gB(EE4 / 2 / 256, NN / 128);       // (8, 64) — dual column stream
    phaseB<<<gB, 256>>>(X4, ker, (const float4*)Ri, (const float4*)ev, out);

    phaseC<<<PC_BLOCKS, 256>>>(X4, ker, (const float4*)Ro, out);
}

// round 13
// speedup vs baseline: 1.0080x; 1.0080x over previous
#include <cuda_runtime.h>

#define NN 8192
#define EE 16384
#define EE4 (EE / 4)

// g_uv[0..EE) = u = e.*(Ro^T a);  g_uv[EE..2EE) = v = e.*(Ri^T b)
__device__ float g_uv[2 * EE];
__device__ unsigned int g_tickets[2];   // [0]=phaseB, [1]=phaseC

// ---------------- Phase A: u from Ro (column reduce, R11-proven) -----------
// u[e] = ev[e] * sum_n Ro[n,e]*a[n],  a = X.k0 inline.
#define PA_CHUNK 128
__global__ __launch_bounds__(256) void phaseA(
    const float4* __restrict__ X4, const float* __restrict__ ker,
    const float* __restrict__ Ro, const float* __restrict__ ev)
{
    __shared__ float sa[PA_CHUNK];
    int tid = threadIdx.x;
    int e   = blockIdx.x * 256 + tid;
    int n0  = blockIdx.y * PA_CHUNK;

    if (tid < PA_CHUNK) {
        float4 x = X4[n0 + tid];
        sa[tid] = x.x * ker[0] + x.y * ker[1] + x.z * ker[2] + x.w * ker[3];
    }
    __syncthreads();

    const float* ro = Ro + (size_t)n0 * EE + e;
    float so = 0.0f;
#pragma unroll 8
    for (int j = 0; j < PA_CHUNK; j++)
        so += __ldcs(ro + (size_t)j * EE) * sa[j];

    atomicAdd(&g_uv[e], ev[e] * so);
}

// ---------------- Phase B: single pass over Ri (persistent tickets) --------
// One load of Ri[n,e] feeds BOTH  v[e] += Ri[n,e]*b[n]  (column reduce)
// and  out[n] += Ri[n,e]*u[e]  (row reduce via shfl butterfly + atomic).
// Tiles: 64 rows x 1024 cols (256 KB), 2048 tiles, ticket-dispatched to 1184
// resident blocks — removes the single-wave spread exposure of R11's B.
#define BT_ROWS 64
#define B_COLG  (EE4 / 256)                 // 16 column groups
#define B_TILES ((NN / BT_ROWS) * B_COLG)   // 2048
#define B_BLOCKS (148 * 8)
__global__ __launch_bounds__(256) void phaseB(
    const float4* __restrict__ X4, const float* __restrict__ ker,
    const float4* __restrict__ Ri4, const float4* __restrict__ ev4,
    float* __restrict__ out)
{
    __shared__ float sb[BT_ROWS];
    __shared__ float sred[BT_ROWS][8];
    __shared__ int sTile;
    int tid  = threadIdx.x;
    int lane = tid & 31;
    int wid  = tid >> 5;

    for (;;) {
        if (tid == 0) sTile = (int)atomicAdd(&g_tickets[0], 1u);
        __syncthreads();
        int tile = sTile;
        if (tile >= B_TILES) break;

        int e4 = (tile % B_COLG) * 256 + tid;   // float4 column index
        int n0 = (tile / B_COLG) * BT_ROWS;

        if (tid < BT_ROWS) {
            float4 x = X4[n0 + tid];
            sb[tid] = x.x * ker[4] + x.y * ker[5] + x.z * ker[6] + x.w * ker[7];
        }
        __syncthreads();

        float4 u = *reinterpret_cast<const float4*>(&g_uv[4 * e4]);  // final after A
        float4 si = make_float4(0.f, 0.f, 0.f, 0.f);
        const float4* ri = Ri4 + (size_t)n0 * EE4 + e4;

#pragma unroll 4
        for (int j = 0; j < BT_ROWS; j++) {
            float4 t = __ldcs(ri + (size_t)j * EE4);
            float B = sb[j];
            si.x += t.x * B; si.y += t.y * B; si.z += t.z * B; si.w += t.w * B;
            float r = t.x * u.x + t.y * u.y + t.z * u.z + t.w * u.w;
            r += __shfl_xor_sync(0xffffffffu, r, 16);
            r += __shfl_xor_sync(0xffffffffu, r, 8);
            r += __shfl_xor_sync(0xffffffffu, r, 4);
            r += __shfl_xor_sync(0xffffffffu, r, 2);
            r += __shfl_xor_sync(0xffffffffu, r, 1);
            if (lane == 0) sred[j][wid] = r;
        }

        float4 w = ev4[e4];
        int a = EE + 4 * e4;
        atomicAdd(&g_uv[a + 0], w.x * si.x);
        atomicAdd(&g_uv[a + 1], w.y * si.y);
        atomicAdd(&g_uv[a + 2], w.z * si.z);
        atomicAdd(&g_uv[a + 3], w.w * si.w);

        __syncthreads();
        if (tid < BT_ROWS) {
            float val = sred[tid][0] + sred[tid][1] + sred[tid][2] + sred[tid][3]
                      + sred[tid][4] + sred[tid][5] + sred[tid][6] + sred[tid][7];
            atomicAdd(&out[n0 + tid], val);
        }
        // next iteration's barrier after the ticket read orders sred reads
        // before the next tile's sred writes (which sit behind two barriers)
    }
}

// ---------------- Phase C: out += Ro.v + c (proven, own ticket) ------------
#define RPB 4
#define NTILES (NN / RPB)
#define PC_BLOCKS (148 * 4)
__global__ __launch_bounds__(256) void phaseC(
    const float4* __restrict__ X4, const float* __restrict__ ker,
    const float4* __restrict__ Ro4, float* __restrict__ out)
{
    __shared__ float red[RPB][256];
    __shared__ int sTile;
    int tid = threadIdx.x;

    const float4* v4 = reinterpret_cast<const float4*>(g_uv) + EE4;

    for (;;) {
        if (tid == 0) sTile = (int)atomicAdd(&g_tickets[1], 1u);
        __syncthreads();
        int tile = sTile;
        if (tile >= NTILES) break;
        int n0 = tile * RPB;

        float s[RPB];
#pragma unroll
        for (int r = 0; r < RPB; r++) s[r] = 0.0f;

#pragma unroll 4
        for (int it = 0; it < EE4 / 256; it++) {
            int e4 = it * 256 + tid;
            float4 v = v4[e4];                 // L2-hot (64 KB)
#pragma unroll
            for (int r = 0; r < RPB; r++) {
                float4 b = __ldcs(Ro4 + (size_t)(n0 + r) * EE4 + e4);
                s[r] += b.x * v.x + b.y * v.y + b.z * v.z + b.w * v.w;
            }
        }

#pragma unroll
        for (int r = 0; r < RPB; r++) red[r][tid] = s[r];
        __syncthreads();
        for (int st = 128; st > 0; st >>= 1) {
            if (tid < st) {
#pragma unroll
                for (int r = 0; r < RPB; r++) red[r][tid] += red[r][tid + st];
            }
            __syncthreads();
        }
        if (tid < RPB) {
            int n = n0 + tid;
            float4 x = X4[n];
            out[n] = out[n] + red[tid][0]      // out already holds Ri.u from B
                   + x.x * ker[8] + x.y * ker[9] + x.z * ker[10] + x.w * ker[11];
        }
        __syncthreads();
    }
}

extern "C" void kernel_launch(void* const* d_in, const int* in_sizes, int n_in,
                              void* d_out, int out_size) {
    const float4* X4  = (const float4*)d_in[0];
    const float*  ev  = (const float*)d_in[1];
    const float*  Ri  = (const float*)d_in[2];
    const float*  Ro  = (const float*)d_in[3];
    const float*  ker = (const float*)d_in[4];
    float* out = (float*)d_out;

    void* uvptr = nullptr;
    cudaGetSymbolAddress(&uvptr, g_uv);
    cudaMemsetAsync(uvptr, 0, 2 * EE * sizeof(float));
    void* tkptr = nullptr;
    cudaGetSymbolAddress(&tkptr, g_tickets);
    cudaMemsetAsync(tkptr, 0, 2 * sizeof(unsigned int));
    cudaMemsetAsync(out, 0, (size_t)out_size * sizeof(float));

    dim3 gA(EE / 256, NN / PA_CHUNK);     // (64, 64) — R11-proven
    phaseA<<<gA, 256>>>(X4, ker, Ro, ev);

    phaseB<<<B_BLOCKS, 256>>>(X4, ker, (const float4*)Ri, (const float4*)ev, out);

    phaseC<<<PC_BLOCKS, 256>>>(X4, ker, (const float4*)Ro, out);
}

// round 14
// speedup vs baseline: 1.0315x; 1.0233x over previous
#include <cuda_runtime.h>

#define NN 8192
#define EE 16384
#define EE4 (EE / 4)

// g_uv[0..EE) = u = e.*(Ro^T a);  g_uv[EE..2EE) = v = e.*(Ri^T b)
__device__ float g_uv[2 * EE];
__device__ unsigned int g_ticket;   // phase C tile dispatcher

// ---------------- Phase A: u from Ro (column reduce, unroll 16) ------------
// u[e] = ev[e] * sum_n Ro[n,e]*a[n],  a = X.k0 inline.
#define PA_CHUNK 128
__global__ __launch_bounds__(256) void phaseA(
    const float4* __restrict__ X4, const float* __restrict__ ker,
    const float* __restrict__ Ro, const float* __restrict__ ev)
{
    __shared__ float sa[PA_CHUNK];
    int tid = threadIdx.x;
    int e   = blockIdx.x * 256 + tid;
    int n0  = blockIdx.y * PA_CHUNK;

    if (tid < PA_CHUNK) {
        float4 x = X4[n0 + tid];
        sa[tid] = x.x * ker[0] + x.y * ker[1] + x.z * ker[2] + x.w * ker[3];
    }
    __syncthreads();

    const float* ro = Ro + (size_t)n0 * EE + e;
    float so = 0.0f;
#pragma unroll 16
    for (int j = 0; j < PA_CHUNK; j++)
        so += __ldcs(ro + (size_t)j * EE) * sa[j];

    atomicAdd(&g_uv[e], ev[e] * so);
}

// ---------------- Phase B: single pass over Ri (fused, 3-shfl reduce) ------
// One load of Ri[n,e] feeds BOTH  v[e] += Ri[n,e]*b[n]  (column reduce)
// and  out[n] += Ri[n,e]*u[e]  (row reduce). Row reduce: 3-step xor butterfly
// (masks 16/8/4) leaves lanes 0-3 holding the 4 residue-class partials; 32
// partials/row land in padded sred (stride 33 -> conflict-free final read).
__global__ __launch_bounds__(256) void phaseB(
    const float4* __restrict__ X4, const float* __restrict__ ker,
    const float4* __restrict__ Ri4, const float4* __restrict__ ev4,
    float* __restrict__ out)
{
    __shared__ float sb[128];
    __shared__ float sred[128][33];
    int tid  = threadIdx.x;
    int lane = tid & 31;
    int wid  = tid >> 5;
    int e4   = blockIdx.x * 256 + tid;      // float4 column index
    int n0   = blockIdx.y * 128;

    if (tid < 128) {
        float4 x = X4[n0 + tid];
        sb[tid] = x.x * ker[4] + x.y * ker[5] + x.z * ker[6] + x.w * ker[7];
    }
    __syncthreads();

    float4 u = *reinterpret_cast<const float4*>(&g_uv[4 * e4]);   // final after A
    float4 si = make_float4(0.f, 0.f, 0.f, 0.f);
    const float4* ri = Ri4 + (size_t)n0 * EE4 + e4;

#pragma unroll 8
    for (int j = 0; j < 128; j++) {
        float4 t = __ldcs(ri + (size_t)j * EE4);
        float B = sb[j];
        si.x += t.x * B; si.y += t.y * B; si.z += t.z * B; si.w += t.w * B;
        float r = t.x * u.x + t.y * u.y + t.z * u.z + t.w * u.w;
        r += __shfl_xor_sync(0xffffffffu, r, 16);
        r += __shfl_xor_sync(0xffffffffu, r, 8);
        r += __shfl_xor_sync(0xffffffffu, r, 4);
        if (lane < 4) sred[j][wid * 4 + lane] = r;
    }

    float4 w = ev4[e4];
    int a = EE + 4 * e4;
    atomicAdd(&g_uv[a + 0], w.x * si.x);
    atomicAdd(&g_uv[a + 1], w.y * si.y);
    atomicAdd(&g_uv[a + 2], w.z * si.z);
    atomicAdd(&g_uv[a + 3], w.w * si.w);

    __syncthreads();
    if (tid < 128) {
        float val = 0.0f;
#pragma unroll
        for (int k = 0; k < 32; k++) val += sred[tid][k];
        atomicAdd(&out[n0 + tid], val);
    }
}

// ---------------- Phase C: out += Ro.v + c (UNCHANGED, proven) -------------
#define RPB 4
#define NTILES (NN / RPB)
#define PC_BLOCKS (148 * 4)
__global__ __launch_bounds__(256) void phaseC(
    const float4* __restrict__ X4, const float* __restrict__ ker,
    const float4* __restrict__ Ro4, float* __restrict__ out)
{
    __shared__ float red[RPB][256];
    __shared__ int sTile;
    int tid = threadIdx.x;

    const float4* v4 = reinterpret_cast<const float4*>(g_uv) + EE4;

    for (;;) {
        if (tid == 0) sTile = (int)atomicAdd(&g_ticket, 1u);
        __syncthreads();
        int tile = sTile;
        if (tile >= NTILES) break;
        int n0 = tile * RPB;

        float s[RPB];
#pragma unroll
        for (int r = 0; r < RPB; r++) s[r] = 0.0f;

#pragma unroll 4
        for (int it = 0; it < EE4 / 256; it++) {
            int e4 = it * 256 + tid;
            float4 v = v4[e4];                 // L2-hot (64 KB)
#pragma unroll
            for (int r = 0; r < RPB; r++) {
                float4 b = __ldcs(Ro4 + (size_t)(n0 + r) * EE4 + e4);
                s[r] += b.x * v.x + b.y * v.y + b.z * v.z + b.w * v.w;
            }
        }

#pragma unroll
        for (int r = 0; r < RPB; r++) red[r][tid] = s[r];
        __syncthreads();
        for (int st = 128; st > 0; st >>= 1) {
            if (tid < st) {
#pragma unroll
                for (int r = 0; r < RPB; r++) red[r][tid] += red[r][tid + st];
            }
            __syncthreads();
        }
        if (tid < RPB) {
            int n = n0 + tid;
            float4 x = X4[n];
            out[n] = out[n] + red[tid][0]      // out already holds Ri.u from B
                   + x.x * ker[8] + x.y * ker[9] + x.z * ker[10] + x.w * ker[11];
        }
        __syncthreads();
    }
}

extern "C" void kernel_launch(void* const* d_in, const int* in_sizes, int n_in,
                              void* d_out, int out_size) {
    const float4* X4  = (const float4*)d_in[0];
    const float*  ev  = (const float*)d_in[1];
    const float*  Ri  = (const float*)d_in[2];
    const float*  Ro  = (const float*)d_in[3];
    const float*  ker = (const float*)d_in[4];
    float* out = (float*)d_out;

    void* uvptr = nullptr;
    cudaGetSymbolAddress(&uvptr, g_uv);
    cudaMemsetAsync(uvptr, 0, 2 * EE * sizeof(float));
    void* tkptr = nullptr;
    cudaGetSymbolAddress(&tkptr, g_ticket);
    cudaMemsetAsync(tkptr, 0, sizeof(unsigned int));
    cudaMemsetAsync(out, 0, (size_t)out_size * sizeof(float));

    dim3 gA(EE / 256, NN / PA_CHUNK);     // (64, 64)
    phaseA<<<gA, 256>>>(X4, ker, Ro, ev);

    dim3 gB(EE4 / 256, NN / 128);         // (16, 64)
    phaseB<<<gB, 256>>>(X4, ker, (const float4*)Ri, (const float4*)ev, out);

    phaseC<<<PC_BLOCKS, 256>>>(X4, ker, (const float4*)Ro, out);
}

// round 15
// speedup vs baseline: 1.0400x; 1.0083x over previous
#include <cuda_runtime.h>

#define NN 8192
#define EE 16384
#define EE4 (EE / 4)

// g_uv[0..EE) = u = e.*(Ro^T a);  g_uv[EE..2EE) = v = e.*(Ri^T b)
__device__ float g_uv[2 * EE];
__device__ unsigned int g_ticket;   // phase C tile dispatcher

// ---------------- Phase A: u from Ro (column reduce, unroll 16 — proven) ---
// u[e] = ev[e] * sum_n Ro[n,e]*a[n],  a = X.k0 inline.
#define PA_CHUNK 128
__global__ __launch_bounds__(256) void phaseA(
    const float4* __restrict__ X4, const float* __restrict__ ker,
    const float* __restrict__ Ro, const float* __restrict__ ev)
{
    __shared__ float sa[PA_CHUNK];
    int tid = threadIdx.x;
    int e   = blockIdx.x * 256 + tid;
    int n0  = blockIdx.y * PA_CHUNK;

    if (tid < PA_CHUNK) {
        float4 x = X4[n0 + tid];
        sa[tid] = x.x * ker[0] + x.y * ker[1] + x.z * ker[2] + x.w * ker[3];
    }
    __syncthreads();

    const float* ro = Ro + (size_t)n0 * EE + e;
    float so = 0.0f;
#pragma unroll 16
    for (int j = 0; j < PA_CHUNK; j++)
        so += __ldcs(ro + (size_t)j * EE) * sa[j];

    atomicAdd(&g_uv[e], ev[e] * so);
}

// ---------------- Phase B: single pass over Ri (R11 shape, unroll 8) -------
// One load of Ri[n,e] feeds BOTH  v[e] += Ri[n,e]*b[n]  (column reduce)
// and  out[n] += Ri[n,e]*u[e]  (row reduce: 5-step shfl butterfly -> compact
// sred[128][8] -> one spread atomicAdd per row).
__global__ __launch_bounds__(256) void phaseB(
    const float4* __restrict__ X4, const float* __restrict__ ker,
    const float4* __restrict__ Ri4, const float4* __restrict__ ev4,
    float* __restrict__ out)
{
    __shared__ float sb[128];
    __shared__ float sred[128][8];
    int tid  = threadIdx.x;
    int lane = tid & 31;
    int wid  = tid >> 5;
    int e4   = blockIdx.x * 256 + tid;      // float4 column index
    int n0   = blockIdx.y * 128;

    if (tid < 128) {
        float4 x = X4[n0 + tid];
        sb[tid] = x.x * ker[4] + x.y * ker[5] + x.z * ker[6] + x.w * ker[7];
    }
    __syncthreads();

    float4 u = *reinterpret_cast<const float4*>(&g_uv[4 * e4]);   // final after A
    float4 si = make_float4(0.f, 0.f, 0.f, 0.f);
    const float4* ri = Ri4 + (size_t)n0 * EE4 + e4;

#pragma unroll 8
    for (int j = 0; j < 128; j++) {
        float4 t = __ldcs(ri + (size_t)j * EE4);
        float B = sb[j];
        si.x += t.x * B; si.y += t.y * B; si.z += t.z * B; si.w += t.w * B;
        float r = t.x * u.x + t.y * u.y + t.z * u.z + t.w * u.w;
        r += __shfl_xor_sync(0xffffffffu, r, 16);
        r += __shfl_xor_sync(0xffffffffu, r, 8);
        r += __shfl_xor_sync(0xffffffffu, r, 4);
        r += __shfl_xor_sync(0xffffffffu, r, 2);
        r += __shfl_xor_sync(0xffffffffu, r, 1);
        if (lane == 0) sred[j][wid] = r;
    }

    float4 w = ev4[e4];
    int a = EE + 4 * e4;
    atomicAdd(&g_uv[a + 0], w.x * si.x);
    atomicAdd(&g_uv[a + 1], w.y * si.y);
    atomicAdd(&g_uv[a + 2], w.z * si.z);
    atomicAdd(&g_uv[a + 3], w.w * si.w);

    __syncthreads();
    if (tid < 128) {
        float val = sred[tid][0] + sred[tid][1] + sred[tid][2] + sred[tid][3]
                  + sred[tid][4] + sred[tid][5] + sred[tid][6] + sred[tid][7];
        atomicAdd(&out[n0 + tid], val);
    }
}

// ---------------- Phase C: out += Ro.v + c (UNCHANGED, proven) -------------
#define RPB 4
#define NTILES (NN / RPB)
#define PC_BLOCKS (148 * 4)
__global__ __launch_bounds__(256) void phaseC(
    const float4* __restrict__ X4, const float* __restrict__ ker,
    const float4* __restrict__ Ro4, float* __restrict__ out)
{
    __shared__ float red[RPB][256];
    __shared__ int sTile;
    int tid = threadIdx.x;

    const float4* v4 = reinterpret_cast<const float4*>(g_uv) + EE4;

    for (;;) {
        if (tid == 0) sTile = (int)atomicAdd(&g_ticket, 1u);
        __syncthreads();
        int tile = sTile;
        if (tile >= NTILES) break;
        int n0 = tile * RPB;

        float s[RPB];
#pragma unroll
        for (int r = 0; r < RPB; r++) s[r] = 0.0f;

#pragma unroll 4
        for (int it = 0; it < EE4 / 256; it++) {
            int e4 = it * 256 + tid;
            float4 v = v4[e4];                 // L2-hot (64 KB)
#pragma unroll
            for (int r = 0; r < RPB; r++) {
                float4 b = __ldcs(Ro4 + (size_t)(n0 + r) * EE4 + e4);
                s[r] += b.x * v.x + b.y * v.y + b.z * v.z + b.w * v.w;
            }
        }

#pragma unroll
        for (int r = 0; r < RPB; r++) red[r][tid] = s[r];
        __syncthreads();
        for (int st = 128; st > 0; st >>= 1) {
            if (tid < st) {
#pragma unroll
                for (int r = 0; r < RPB; r++) red[r][tid] += red[r][tid + st];
            }
            __syncthreads();
        }
        if (tid < RPB) {
            int n = n0 + tid;
            float4 x = X4[n];
            out[n] = out[n] + red[tid][0]      // out already holds Ri.u from B
                   + x.x * ker[8] + x.y * ker[9] + x.z * ker[10] + x.w * ker[11];
        }
        __syncthreads();
    }
}

extern "C" void kernel_launch(void* const* d_in, const int* in_sizes, int n_in,
                              void* d_out, int out_size) {
    const float4* X4  = (const float4*)d_in[0];
    const float*  ev  = (const float*)d_in[1];
    const float*  Ri  = (const float*)d_in[2];
    const float*  Ro  = (const float*)d_in[3];
    const float*  ker = (const float*)d_in[4];
    float* out = (float*)d_out;

    void* uvptr = nullptr;
    cudaGetSymbolAddress(&uvptr, g_uv);
    cudaMemsetAsync(uvptr, 0, 2 * EE * sizeof(float));
    void* tkptr = nullptr;
    cudaGetSymbolAddress(&tkptr, g_ticket);
    cudaMemsetAsync(tkptr, 0, sizeof(unsigned int));
    cudaMemsetAsync(out, 0, (size_t)out_size * sizeof(float));

    dim3 gA(EE / 256, NN / PA_CHUNK);     // (64, 64)
    phaseA<<<gA, 256>>>(X4, ker, Ro, ev);

    dim3 gB(EE4 / 256, NN / 128);         // (16, 64)
    phaseB<<<gB, 256>>>(X4, ker, (const float4*)Ri, (const float4*)ev, out);

    phaseC<<<PC_BLOCKS, 256>>>(X4, ker, (const float4*)Ro, out);
}